// round 9
// baseline (speedup 1.0000x reference)
#include <cuda_runtime.h>

#define B_  32
#define D_  32
#define H_  256
#define W_  256
#define K_  512
#define TT  32                     // pair-tile size
#define NT  (K_ / TT)              // 16 tiles per image
#define NPAIRS (NT * (NT + 1) / 2) // 136 (ti <= tj)
#define GTHREADS 256
#define LTHREADS 64                // loss: 8(kg) x 8(lg), 4x4 outputs each

typedef unsigned long long ull;

// Scratch: gathered pred, TRANSPOSED [B][D][K] (k contiguous), norms, tags.
__device__ float g_predT[B_ * D_ * K_];  // 2 MB
__device__ float g_ns[B_ * K_];
__device__ int   g_tag[B_ * K_];

__device__ __forceinline__ float tanh_approx(float x) {
    float y;
    asm("tanh.approx.f32 %0, %1;" : "=f"(y) : "f"(x));
    return y;
}
__device__ __forceinline__ void fma2(ull& acc, ull a, ull b) {
    asm("fma.rn.f32x2 %0, %1, %2, %0;" : "+l"(acc) : "l"(a), "l"(b));
}

union F4U { float4 f; ull u[2]; };
union UF  { ull u; float f[2]; };

// Four threads per (b, k): each gathers 8 channels, writes d-major,
// partial ||p||^2 combined via 2-stage shfl. dtype (int32 vs int64)
// detected from data: int64 => high dword of every value is 0.
__global__ void gather_kernel(const float* __restrict__ ebd,
                              const void* __restrict__ kpts_raw,
                              const void* __restrict__ tags_raw,
                              float* __restrict__ out) {
    if (blockIdx.x == 0 && threadIdx.x == 0) out[0] = 0.0f;

    int tid = blockIdx.x * blockDim.x + threadIdx.x;   // 4*(b*K + k) + h
    if (tid >= B_ * K_ * 4) return;
    int idx = tid >> 2;            // point index b*K + k
    int h   = tid & 3;             // d-quarter

    const unsigned* kd = (const unsigned*)kpts_raw;
    bool is64 = true;
#pragma unroll
    for (int i = 1; i < 32; i += 2) is64 &= (__ldg(kd + i) == 0u);

    int r, c, tg;
    if (is64) {
        const long long* kp  = (const long long*)kpts_raw;
        const long long* tgp = (const long long*)tags_raw;
        r  = (int)kp[(size_t)idx * 2 + 0];
        c  = (int)kp[(size_t)idx * 2 + 1];
        tg = (int)tgp[idx];
    } else {
        const int* kp  = (const int*)kpts_raw;
        const int* tgp = (const int*)tags_raw;
        r  = kp[(size_t)idx * 2 + 0];
        c  = kp[(size_t)idx * 2 + 1];
        tg = tgp[idx];
    }
    r = min(max(r, 0), H_ - 1);
    c = min(max(c, 0), W_ - 1);

    int b = idx >> 9;
    int k = idx & (K_ - 1);
    const int d0 = h * (D_ / 4);
    const float* base = ebd + (size_t)b * D_ * H_ * W_ + (size_t)d0 * (H_ * W_)
                            + (size_t)r * W_ + (size_t)c;
    float* dstT = g_predT + (size_t)b * D_ * K_ + (size_t)d0 * K_ + k;
    float ns = 0.0f;
#pragma unroll
    for (int d = 0; d < D_ / 4; ++d) {
        float x = base[(size_t)d * (H_ * W_)];
        dstT[(size_t)d * K_] = x;
        ns += x * x;
    }
    ns += __shfl_xor_sync(0xffffffffu, ns, 1);
    ns += __shfl_xor_sync(0xffffffffu, ns, 2);
    if (h == 0) {
        g_ns[idx]  = ns;
        g_tag[idx] = tg;
    }
}

// Symmetry-halved pairwise loss, 32x32 tile pairs, 4x4 outputs per thread.
// J tile stored DUPLICATED in smem ((l,l) adjacent) so FMA2's broadcast
// operand is a direct LDS.128 - no register packing in the inner loop.
// Thread t: k in {k0..k0+3} (k0=(t&7)*4), l in {l0..l0+3} (l0=(t>>3)*4).
// psim = 2/(1+exp(x)) = 1 - tanh(x/2)  ->  e = tanh(arg) - neq.
__global__ __launch_bounds__(LTHREADS) void loss_kernel(float* __restrict__ out) {
    const int b = blockIdx.x / NPAIRS;
    int p = blockIdx.x % NPAIRS;
    int ti = 0;
    while (p >= NT - ti) { p -= (NT - ti); ++ti; }
    const int tj = ti + p;

    __shared__ float sI [D_ * TT];      // [d][k]        4 KB
    __shared__ float sJd[D_ * TT * 2];  // [d][2l dup]   8 KB
    __shared__ float nsI[TT], nsJ[TT];
    __shared__ int   tgI[TT], tgJ[TT];
    __shared__ float wsum[2];

    const int t = threadIdx.x;
    const float* srcI = g_predT + (size_t)b * D_ * K_ + ti * TT;
    const float* srcJ = g_predT + (size_t)b * D_ * K_ + tj * TT;

    // Fill: 256 float4 per tile, 4 per thread. I row d = 8 float4,
    // J written duplicated: row d = 16 float4.
#pragma unroll
    for (int rr = 0; rr < 4; ++rr) {
        int idx4 = t + rr * LTHREADS;     // 0..255
        int d  = idx4 >> 3;
        int j4 = idx4 & 7;
        float4 vi = *(const float4*)(srcI + (size_t)d * K_ + j4 * 4);
        ((float4*)sI)[idx4] = vi;
        float4 vj = *(const float4*)(srcJ + (size_t)d * K_ + j4 * 4);
        ((float4*)sJd)[d * 16 + j4 * 2]     = make_float4(vj.x, vj.x, vj.y, vj.y);
        ((float4*)sJd)[d * 16 + j4 * 2 + 1] = make_float4(vj.z, vj.z, vj.w, vj.w);
    }
    {
        const int baseI = b * K_ + ti * TT;
        const int baseJ = b * K_ + tj * TT;
        if (t < TT) {
            nsI[t] = g_ns[baseI + t];    tgI[t] = g_tag[baseI + t];
        } else {
            nsJ[t - TT] = g_ns[baseJ + t - TT];
            tgJ[t - TT] = g_tag[baseJ + t - TT];
        }
    }
    __syncthreads();

    const int k0 = (t & 7) * 4;
    const int l0 = (t >> 3) * 4;

    // acc2[kp][j]: packed k-pair (k0+2kp, k0+2kp+1) x l_{l0+j}.
    ull acc2[2][4];
#pragma unroll
    for (int i = 0; i < 2; ++i)
#pragma unroll
        for (int j = 0; j < 4; ++j) acc2[i][j] = 0ull;

    const float* pI = sI  + k0;
    const float* pJ = sJd + 2 * l0;
#pragma unroll
    for (int d = 0; d < D_; ++d) {
        F4U ka, la, lb;
        ka.f = *(const float4*)(pI + d * TT);           // (k0..k0+3)
        la.f = *(const float4*)(pJ + d * (2 * TT));     // (l0,l0),(l0+1,l0+1)
        lb.f = *(const float4*)(pJ + d * (2 * TT) + 4); // (l0+2,l0+2),(l0+3,l0+3)
        ull ku[2] = {ka.u[0], ka.u[1]};
        ull lu[4] = {la.u[0], la.u[1], lb.u[0], lb.u[1]};
#pragma unroll
        for (int kp = 0; kp < 2; ++kp)
#pragma unroll
            for (int j = 0; j < 4; ++j)
                fma2(acc2[kp][j], ku[kp], lu[j]);
    }

    // Epilogue: 16 pairs. arg = (nsk + nsl - 2*dot)/64; e = tanh(arg) - neq.
    float nsk2[4], nsl2[4];
    int   tgk[4], tgl[4];
#pragma unroll
    for (int i = 0; i < 4; ++i) {
        nsk2[i] = nsI[k0 + i] * (1.0f / 64.0f);
        tgk[i]  = tgI[k0 + i];
        nsl2[i] = nsJ[l0 + i] * (1.0f / 64.0f);
        tgl[i]  = tgJ[l0 + i];
    }

    float lsum = 0.0f;
#pragma unroll
    for (int kp = 0; kp < 2; ++kp) {
#pragma unroll
        for (int j = 0; j < 4; ++j) {
            UF v; v.u = acc2[kp][j];
            int i0 = 2 * kp, i1 = 2 * kp + 1;
            float arg0 = fmaf(v.f[0], -1.0f / 32.0f, nsk2[i0] + nsl2[j]);
            float arg1 = fmaf(v.f[1], -1.0f / 32.0f, nsk2[i1] + nsl2[j]);
            float e0 = tanh_approx(arg0) - ((tgk[i0] != tgl[j]) ? 1.0f : 0.0f);
            float e1 = tanh_approx(arg1) - ((tgk[i1] != tgl[j]) ? 1.0f : 0.0f);
            lsum += e0 * e0 + e1 * e1;
        }
    }

    // Block reduction (2 warps) + weighted atomic.
#pragma unroll
    for (int o = 16; o > 0; o >>= 1)
        lsum += __shfl_down_sync(0xffffffffu, lsum, o);
    if ((t & 31) == 0) wsum[t >> 5] = lsum;
    __syncthreads();
    if (t == 0) {
        float w = (ti == tj) ? 1.0f : 2.0f;
        atomicAdd(out, (wsum[0] + wsum[1]) * w *
                       (1.0f / ((float)B_ * (float)K_ * (float)K_)));
    }
}

extern "C" void kernel_launch(void* const* d_in, const int* in_sizes, int n_in,
                              void* d_out, int out_size) {
    const float* ebd  = (const float*)d_in[0];
    const void*  kpts = (const void*)d_in[1];
    const void*  tags = (const void*)d_in[2];
    float* out = (float*)d_out;

    (void)in_sizes; (void)n_in; (void)out_size;

    gather_kernel<<<(B_ * K_ * 4 + GTHREADS - 1) / GTHREADS, GTHREADS>>>(ebd, kpts, tags, out);
    loss_kernel<<<B_ * NPAIRS, LTHREADS>>>(out);
}